// round 3
// baseline (speedup 1.0000x reference)
#include <cuda_runtime.h>
#include <cuda_bf16.h>

// ---------------------------------------------------------------------------
// SparseGraphSAGE on GB300 — round 3.
//   GEMM: 64x128 block tile, 128 threads, 8x8 per-thread tile (4 row-pairs x
//   8 cols) with packed fp32 FFMA2. Cuts smem crossbar bytes/MAC ~1.8x vs R2.
// Pipeline: zero_cnt -> build buckets -> spmm(h) -> gemm1(relu) ->
//           spmm(h1) -> gemm3(h2,P,Q fused) -> decode(pos+neg)
// ---------------------------------------------------------------------------

#define NN_MAX 50000
#define CAP 64          // per-row edge capacity; mean deg=16, P(>64) ~ 1e-19

__device__ int   g_cnt[NN_MAX];
__device__ int   g_col[NN_MAX * CAP];
__device__ float g_val[NN_MAX * CAP];
__device__ float g_deginv[NN_MAX];
__device__ __align__(16) float g_t [NN_MAX * 128];
__device__ __align__(16) float g_h1[NN_MAX * 128];
__device__ __align__(16) float g_P [NN_MAX * 128];
__device__ __align__(16) float g_Q [NN_MAX * 128];

// ------------------------------ f32x2 helpers ------------------------------
__device__ __forceinline__ unsigned long long f2_fma(unsigned long long a,
                                                     unsigned long long b,
                                                     unsigned long long c) {
    unsigned long long d;
    asm("fma.rn.f32x2 %0, %1, %2, %3;" : "=l"(d) : "l"(a), "l"(b), "l"(c));
    return d;
}
__device__ __forceinline__ unsigned long long f2_dup(float x) {
    unsigned long long d;
    unsigned xi = __float_as_uint(x);
    asm("mov.b64 %0, {%1, %1};" : "=l"(d) : "r"(xi));
    return d;
}
__device__ __forceinline__ float f2_lo(unsigned long long a) {
    return __uint_as_float((unsigned)a);
}
__device__ __forceinline__ float f2_hi(unsigned long long a) {
    return __uint_as_float((unsigned)(a >> 32));
}

// ------------------------------ smem geometry ------------------------------
// Ws: 128 x 128 (k-major copy of W)                    = 65536 B
// As: 128 x 66  (transposed A tile: As[k*66 + m])      = 33792 B
#define AS_PAD 66
#define WS_FLOATS (128 * 128)
#define AS_FLOATS (128 * AS_PAD)
#define GEMM_SMEM_BYTES ((WS_FLOATS + AS_FLOATS) * 4)
#define GEMM_THREADS 128

__device__ __forceinline__ void load_W(float* Ws, const float* __restrict__ W, int tid) {
    const float4* W4 = (const float4*)W;
    float4* Ws4 = (float4*)Ws;
#pragma unroll
    for (int i = 0; i < 32; i++)
        Ws4[i * GEMM_THREADS + tid] = W4[i * GEMM_THREADS + tid];
}

// Load 64-row A tile into transposed smem layout As[k][m].
__device__ __forceinline__ void load_A(float* As, const float* __restrict__ A,
                                       const float* __restrict__ scale,
                                       int m_base, int M, int tid) {
    const float4* A4 = (const float4*)A;
#pragma unroll
    for (int i = 0; i < 16; i++) {
        int j  = i * GEMM_THREADS + tid;  // 0..2047
        int c4 = j >> 6;                  // k-group 0..31
        int m  = j & 63;                  // row in tile
        int gm = m_base + m;
        if (gm >= M) gm = M - 1;
        float4 v = A4[gm * 32 + c4];
        if (scale != nullptr) {
            float s = scale[gm];
            v.x *= s; v.y *= s; v.z *= s; v.w *= s;
        }
        int kb = c4 * 4;
        As[(kb + 0) * AS_PAD + m] = v.x;
        As[(kb + 1) * AS_PAD + m] = v.y;
        As[(kb + 2) * AS_PAD + m] = v.z;
        As[(kb + 3) * AS_PAD + m] = v.w;
    }
}

// Core 64x128x128 MMA: thread (ty,tx) computes 4 row-pairs x 8 cols.
__device__ __forceinline__ void mma_tile(const float* Ws, const float* As,
                                         int m0, int n0,
                                         unsigned long long acc[4][8]) {
#pragma unroll
    for (int rp = 0; rp < 4; rp++)
#pragma unroll
        for (int c = 0; c < 8; c++) acc[rp][c] = 0ull;

#pragma unroll 2
    for (int k = 0; k < 128; k++) {
        float4 wa = *(const float4*)&Ws[k * 128 + n0];
        float4 wb = *(const float4*)&Ws[k * 128 + n0 + 4];
        unsigned long long w[8];
        w[0] = f2_dup(wa.x); w[1] = f2_dup(wa.y);
        w[2] = f2_dup(wa.z); w[3] = f2_dup(wa.w);
        w[4] = f2_dup(wb.x); w[5] = f2_dup(wb.y);
        w[6] = f2_dup(wb.z); w[7] = f2_dup(wb.w);
        const float* ar = &As[k * AS_PAD + m0];
        unsigned long long a0 = *(const unsigned long long*)(ar + 0);
        unsigned long long a1 = *(const unsigned long long*)(ar + 2);
        unsigned long long a2 = *(const unsigned long long*)(ar + 4);
        unsigned long long a3 = *(const unsigned long long*)(ar + 6);
#pragma unroll
        for (int c = 0; c < 8; c++) {
            acc[0][c] = f2_fma(a0, w[c], acc[0][c]);
            acc[1][c] = f2_fma(a1, w[c], acc[1][c]);
            acc[2][c] = f2_fma(a2, w[c], acc[2][c]);
            acc[3][c] = f2_fma(a3, w[c], acc[3][c]);
        }
    }
}

__device__ __forceinline__ void epilogue(float* __restrict__ C,
                                         const unsigned long long acc[4][8],
                                         const float* __restrict__ bias, bool relu,
                                         int m_base, int m0, int n0, int M) {
    float bv[8];
#pragma unroll
    for (int c = 0; c < 8; c++) bv[c] = 0.f;
    if (bias != nullptr) {
        float4 ba = *(const float4*)&bias[n0];
        float4 bb = *(const float4*)&bias[n0 + 4];
        bv[0] = ba.x; bv[1] = ba.y; bv[2] = ba.z; bv[3] = ba.w;
        bv[4] = bb.x; bv[5] = bb.y; bv[6] = bb.z; bv[7] = bb.w;
    }
#pragma unroll
    for (int rp = 0; rp < 4; rp++) {
        int r0 = m_base + m0 + 2 * rp;
        float lo[8], hi[8];
#pragma unroll
        for (int c = 0; c < 8; c++) {
            lo[c] = f2_lo(acc[rp][c]) + bv[c];
            hi[c] = f2_hi(acc[rp][c]) + bv[c];
            if (relu) { lo[c] = fmaxf(lo[c], 0.f); hi[c] = fmaxf(hi[c], 0.f); }
        }
        if (r0 < M) {
            *(float4*)&C[r0 * 128 + n0]     = make_float4(lo[0], lo[1], lo[2], lo[3]);
            *(float4*)&C[r0 * 128 + n0 + 4] = make_float4(lo[4], lo[5], lo[6], lo[7]);
        }
        if (r0 + 1 < M) {
            *(float4*)&C[(r0 + 1) * 128 + n0]     = make_float4(hi[0], hi[1], hi[2], hi[3]);
            *(float4*)&C[(r0 + 1) * 128 + n0 + 4] = make_float4(hi[4], hi[5], hi[6], hi[7]);
        }
    }
}

// -------------------------------- gemm1 ------------------------------------
__global__ __launch_bounds__(GEMM_THREADS)
void k_gemm1(const float* __restrict__ A, const float* __restrict__ scale,
             const float* __restrict__ W, const float* __restrict__ bias,
             float* __restrict__ C, int M) {
    extern __shared__ float sm[];
    float* Ws = sm;
    float* As = sm + WS_FLOATS;
    int tid = threadIdx.x;
    int m_base = blockIdx.x * 64;
    int tx = tid & 15, ty = tid >> 4;
    int n0 = tx * 8, m0 = ty * 8;

    load_W(Ws, W, tid);
    load_A(As, A, scale, m_base, M, tid);
    __syncthreads();

    unsigned long long acc[4][8];
    mma_tile(Ws, As, m0, n0, acc);
    epilogue(C, acc, bias, true, m_base, m0, n0, M);
}

// -------------------------- fused h2 / P / Q --------------------------------
__global__ __launch_bounds__(GEMM_THREADS)
void k_gemm3(const float* __restrict__ A, const float* __restrict__ scale,
             const float* __restrict__ W2, const float* __restrict__ b2,
             float* __restrict__ H2,
             const float* __restrict__ Wd1,
             float* __restrict__ P, float* __restrict__ Q, int M) {
    extern __shared__ float sm[];
    float* Ws = sm;
    float* As = sm + WS_FLOATS;
    int tid = threadIdx.x;
    int m_base = blockIdx.x * 64;
    int tx = tid & 15, ty = tid >> 4;
    int n0 = tx * 8, m0 = ty * 8;

    unsigned long long acc[4][8];

    // phase 1: h2 = (t*deginv) @ W2 + b2
    load_W(Ws, W2, tid);
    load_A(As, A, scale, m_base, M, tid);
    __syncthreads();
    mma_tile(Ws, As, m0, n0, acc);
    epilogue(H2, acc, b2, false, m_base, m0, n0, M);
    __syncthreads();

    // phase 2: P = h2 @ Wd1_top  (h2 written by this block; __syncthreads
    // makes block-local gmem writes visible)
    load_W(Ws, Wd1, tid);
    load_A(As, H2, nullptr, m_base, M, tid);
    __syncthreads();
    mma_tile(Ws, As, m0, n0, acc);
    epilogue(P, acc, nullptr, false, m_base, m0, n0, M);
    __syncthreads();

    // phase 3: Q = h2 @ Wd1_bot  (As already holds the h2 tile)
    load_W(Ws, Wd1 + 128 * 128, tid);
    __syncthreads();
    mma_tile(Ws, As, m0, n0, acc);
    epilogue(Q, acc, nullptr, false, m_base, m0, n0, M);
}

// -------------------------------- zero counters ---------------------------
__global__ void k_zero_cnt(int nn) {
    int i = blockIdx.x * blockDim.x + threadIdx.x;
    if (i < nn) g_cnt[i] = 0;
}

// -------------------------------- bucket scatter --------------------------
__global__ void k_build(const int2* __restrict__ idx, const float* __restrict__ val, int ne) {
    int e = blockIdx.x * blockDim.x + threadIdx.x;
    if (e >= ne) return;
    int2 rc = idx[e];
    float v = val[e];
    int slot = atomicAdd(&g_cnt[rc.x], 1);
    if (slot < CAP) {
        g_col[rc.x * CAP + slot] = rc.y;
        g_val[rc.x * CAP + slot] = v;
    }
}

// -------------------------------- spmm gather -----------------------------
__global__ void k_spmm(const float4* __restrict__ X, float4* __restrict__ Y,
                       float* __restrict__ deginv_out, int nn) {
    int w = (blockIdx.x * blockDim.x + threadIdx.x) >> 5;
    int lane = threadIdx.x & 31;
    if (w >= nn) return;
    int cnt = g_cnt[w];
    if (cnt > CAP) cnt = CAP;
    const int*   cols = &g_col[w * CAP];
    const float* vals = &g_val[w * CAP];
    float4 acc = make_float4(0.f, 0.f, 0.f, 0.f);
    float dsum = 0.f;
#pragma unroll 2
    for (int e = 0; e < cnt; e++) {
        int c = cols[e];
        float v = vals[e];
        float4 x = X[c * 32 + lane];
        acc.x += v * x.x; acc.y += v * x.y; acc.z += v * x.z; acc.w += v * x.w;
        dsum += v;
    }
    Y[w * 32 + lane] = acc;
    if (deginv_out != nullptr && lane == 0)
        deginv_out[w] = 1.0f / fmaxf(dsum, 1.0f);
}

// -------------------------------- decoder (pos+neg fused) ------------------
__global__ void k_decode2(const int* __restrict__ pu, const int* __restrict__ pv,
                          const int* __restrict__ nu, const int* __restrict__ nv,
                          const float4* __restrict__ P, const float4* __restrict__ Q,
                          const float* __restrict__ bd1, const float* __restrict__ Wd2,
                          const float* __restrict__ bd2, float* __restrict__ out, int NP) {
    int w = (blockIdx.x * blockDim.x + threadIdx.x) >> 5;
    int lane = threadIdx.x & 31;
    if (w >= 2 * NP) return;
    int u, v;
    if (w < NP) { u = pu[w]; v = pv[w]; }
    else        { u = nu[w - NP]; v = nv[w - NP]; }
    float4 p = P[u * 32 + lane];
    float4 q = Q[v * 32 + lane];
    float4 b = ((const float4*)bd1)[lane];
    float4 d = ((const float4*)Wd2)[lane];
    float h0 = fmaxf(p.x + q.x + b.x, 0.f);
    float h1 = fmaxf(p.y + q.y + b.y, 0.f);
    float h2 = fmaxf(p.z + q.z + b.z, 0.f);
    float h3 = fmaxf(p.w + q.w + b.w, 0.f);
    float s = h0 * d.x + h1 * d.y + h2 * d.z + h3 * d.w;
#pragma unroll
    for (int o = 16; o > 0; o >>= 1)
        s += __shfl_down_sync(0xffffffff, s, o);
    if (lane == 0) out[w] = s + bd2[0];
}

// -------------------------------- launcher --------------------------------
extern "C" void kernel_launch(void* const* d_in, const int* in_sizes, int n_in,
                              void* d_out, int out_size) {
    int o = (n_in >= 16) ? 1 : 0;   // num_nodes scalar present?

    const int2*  adj   = (const int2*) d_in[0];
    const float* avals = (const float*)d_in[1];
    const float* h     = (const float*)d_in[2 + o];
    const int*   pos_u = (const int*)  d_in[3 + o];
    const int*   pos_v = (const int*)  d_in[4 + o];
    const int*   neg_u = (const int*)  d_in[5 + o];
    const int*   neg_v = (const int*)  d_in[6 + o];
    const float* W1    = (const float*)d_in[7 + o];
    const float* b1    = (const float*)d_in[8 + o];
    const float* W2    = (const float*)d_in[9 + o];
    const float* b2    = (const float*)d_in[10 + o];
    const float* Wd1   = (const float*)d_in[11 + o];
    const float* bd1   = (const float*)d_in[12 + o];
    const float* Wd2   = (const float*)d_in[13 + o];
    const float* bd2   = (const float*)d_in[14 + o];

    const int NE = in_sizes[1];
    const int NN = in_sizes[2 + o] / 128;
    const int NP = in_sizes[3 + o];

    float* out = (float*)d_out;
    float* pos_out = out;           // decode writes pos then neg contiguously
    float* h2      = out + 2 * NP;  // [NN,128]

    static float* p_t = nullptr;
    static float* p_h1 = nullptr;
    static float* p_P = nullptr;
    static float* p_Q = nullptr;
    static float* p_deginv = nullptr;
    static bool init = false;
    if (!init) {
        cudaGetSymbolAddress((void**)&p_t, g_t);
        cudaGetSymbolAddress((void**)&p_h1, g_h1);
        cudaGetSymbolAddress((void**)&p_P, g_P);
        cudaGetSymbolAddress((void**)&p_Q, g_Q);
        cudaGetSymbolAddress((void**)&p_deginv, g_deginv);
        cudaFuncSetAttribute(k_gemm1, cudaFuncAttributeMaxDynamicSharedMemorySize, GEMM_SMEM_BYTES);
        cudaFuncSetAttribute(k_gemm3, cudaFuncAttributeMaxDynamicSharedMemorySize, GEMM_SMEM_BYTES);
        init = true;
    }

    int gemm_blocks = (NN + 63) / 64;

    k_zero_cnt<<<(NN + 255) / 256, 256>>>(NN);
    k_build<<<(NE + 255) / 256, 256>>>(adj, avals, NE);
    k_spmm<<<(NN * 32 + 255) / 256, 256>>>((const float4*)h, (float4*)p_t, p_deginv, NN);
    k_gemm1<<<gemm_blocks, GEMM_THREADS, GEMM_SMEM_BYTES>>>(p_t, p_deginv, W1, b1, p_h1, NN);
    k_spmm<<<(NN * 32 + 255) / 256, 256>>>((const float4*)p_h1, (float4*)p_t, nullptr, NN);
    k_gemm3<<<gemm_blocks, GEMM_THREADS, GEMM_SMEM_BYTES>>>(p_t, p_deginv, W2, b2, h2, Wd1, p_P, p_Q, NN);
    k_decode2<<<(2 * NP * 32 + 255) / 256, 256>>>(pos_u, pos_v, neg_u, neg_v,
                                                  (const float4*)p_P, (const float4*)p_Q,
                                                  bd1, Wd2, bd2, pos_out, NP);
}

// round 5
// speedup vs baseline: 1.3097x; 1.3097x over previous
#include <cuda_runtime.h>
#include <cuda_bf16.h>
#include <cstdint>

// ---------------------------------------------------------------------------
// SparseGraphSAGE on GB300 — round 5: warp-level bf16 MMA (HMMA, sm_80 PTX —
// works on the base sm_103 target, unlike tcgen05 which needs sm_103a).
//   - Weights pre-split (bf16 hi/lo) + pre-transposed to [n][k] once/launch.
//   - GEMM: 128x128 CTA tile, 8 warps (32m x 64n each), mma.sync.m16n8k16,
//     3-product split (hi*hi + hi*lo + lo*hi) -> ~1e-5 relative accuracy.
//   - gemm3 fused: h2 -> (re-split into A smem) -> P -> Q.
// ---------------------------------------------------------------------------

#define NN_MAX 50000
#define CAP 64

__device__ int   g_cnt[NN_MAX];
__device__ int   g_col[NN_MAX * CAP];
__device__ float g_val[NN_MAX * CAP];
__device__ float g_deginv[NN_MAX];
__device__ __align__(16) float g_t [NN_MAX * 128];
__device__ __align__(16) float g_h1[NN_MAX * 128];
__device__ __align__(16) float g_P [NN_MAX * 128];
__device__ __align__(16) float g_Q [NN_MAX * 128];

// pre-split, pre-transposed weights [n][k]: 0=W1, 1=W2, 2=Wd1_top, 3=Wd1_bot
__device__ __align__(16) __nv_bfloat16 g_Whi[4][16384];
__device__ __align__(16) __nv_bfloat16 g_Wlo[4][16384];

// ------------------------------ helpers ------------------------------------
__device__ __forceinline__ uint32_t smem_u32(const void* p) {
    uint32_t a;
    asm("{ .reg .u64 t; cvta.to.shared.u64 t, %1; cvt.u32.u64 %0, t; }"
        : "=r"(a) : "l"(p));
    return a;
}
__device__ __forceinline__ void ldsm_x4(uint32_t addr, uint32_t r[4]) {
    asm volatile("ldmatrix.sync.aligned.m8n8.x4.shared.b16 {%0,%1,%2,%3}, [%4];"
                 : "=r"(r[0]), "=r"(r[1]), "=r"(r[2]), "=r"(r[3]) : "r"(addr));
}
__device__ __forceinline__ void mma16816(float* c, const uint32_t* a,
                                         uint32_t b0, uint32_t b1) {
    asm volatile("mma.sync.aligned.m16n8k16.row.col.f32.bf16.bf16.f32 "
        "{%0,%1,%2,%3}, {%4,%5,%6,%7}, {%8,%9}, {%0,%1,%2,%3};"
        : "+f"(c[0]), "+f"(c[1]), "+f"(c[2]), "+f"(c[3])
        : "r"(a[0]), "r"(a[1]), "r"(a[2]), "r"(a[3]), "r"(b0), "r"(b1));
}

// ------------------------------ smem geometry ------------------------------
// padded pitch 136 bf16 (272 B) -> ldmatrix row addresses land on distinct banks
#define PITCH 136
#define TILE_B (128 * PITCH * 2)     // 34816 bytes per bf16 tile
#define SM_AHI 0
#define SM_ALO (TILE_B)
#define SM_WHI (2 * TILE_B)
#define SM_WLO (3 * TILE_B)
#define SMEM_MMA (4 * TILE_B)        // 139264 bytes

// copy pre-split W [n][k] (bf16, contiguous) into padded smem tiles
__device__ __forceinline__ void load_W(char* smem, const __nv_bfloat16* __restrict__ wh,
                                       const __nv_bfloat16* __restrict__ wl, int tid) {
    const uint32_t* sh = (const uint32_t*)wh;
    const uint32_t* sl = (const uint32_t*)wl;
#pragma unroll 8
    for (int i = 0; i < 32; i++) {
        int idx = i * 256 + tid;          // 0..8191 u32 words
        int n = idx >> 6, kp = idx & 63;  // kp indexes bf16 pairs
        uint32_t off = n * (PITCH * 2) + kp * 4;
        *(uint32_t*)(smem + SM_WHI + off) = sh[idx];
        *(uint32_t*)(smem + SM_WLO + off) = sl[idx];
    }
}

// split f32 A tile (optionally scaled) into bf16 hi/lo padded smem tiles
__device__ __forceinline__ void split_A(char* smem, const float2* __restrict__ A2,
                                        const float* __restrict__ scale,
                                        int m_base, int M, int tid) {
#pragma unroll 4
    for (int i = 0; i < 32; i++) {
        int idx = i * 256 + tid;          // 0..8191 float2
        int ml = idx >> 6, cp = idx & 63;
        int gm = m_base + ml; if (gm >= M) gm = M - 1;
        float2 v = A2[(size_t)gm * 64 + cp];
        if (scale) { float s = scale[gm]; v.x *= s; v.y *= s; }
        __nv_bfloat16 hx = __float2bfloat16(v.x), hy = __float2bfloat16(v.y);
        float rx = v.x - __bfloat162float(hx), ry = v.y - __bfloat162float(hy);
        __nv_bfloat16 lx = __float2bfloat16(rx), ly = __float2bfloat16(ry);
        uint32_t hp = ((uint32_t)__bfloat16_as_ushort(hy) << 16) | __bfloat16_as_ushort(hx);
        uint32_t lp = ((uint32_t)__bfloat16_as_ushort(ly) << 16) | __bfloat16_as_ushort(lx);
        uint32_t off = ml * (PITCH * 2) + cp * 4;
        *(uint32_t*)(smem + SM_AHI + off) = hp;
        *(uint32_t*)(smem + SM_ALO + off) = lp;
    }
}

// 3-pass split MMA over the 128-K tile; acc[2][8][4] per thread
__device__ __forceinline__ void mma_passes(uint32_t sb, int m_off, int n_off,
                                           int lane, float acc[2][8][4]) {
    const uint32_t aoff[3] = {SM_AHI, SM_AHI, SM_ALO};
    const uint32_t woff[3] = {SM_WHI, SM_WLO, SM_WHI};
    uint32_t a_r = lane & 15;
    uint32_t a_k = (lane >> 4) << 3;
    uint32_t b_r = (lane & 7) | ((lane & 16) >> 1);
    uint32_t b_k = lane & 8;
#pragma unroll
    for (int p = 0; p < 3; p++) {
        uint32_t ab = sb + aoff[p];
        uint32_t wb = sb + woff[p];
        uint32_t addrA = ab + ((m_off + a_r) * PITCH + a_k) * 2;
        uint32_t addrB = wb + ((n_off + b_r) * PITCH + b_k) * 2;
#pragma unroll
        for (int ks = 0; ks < 8; ks++) {
            uint32_t a[2][4];
            ldsm_x4(addrA,               a[0]);
            ldsm_x4(addrA + 16 * PITCH * 2, a[1]);
            uint32_t b[4][4];
#pragma unroll
            for (int nt = 0; nt < 4; nt++)
                ldsm_x4(addrB + nt * 16 * PITCH * 2, b[nt]);
#pragma unroll
            for (int mi = 0; mi < 2; mi++)
#pragma unroll
                for (int nt = 0; nt < 4; nt++) {
                    mma16816(acc[mi][2 * nt],     a[mi], b[nt][0], b[nt][1]);
                    mma16816(acc[mi][2 * nt + 1], a[mi], b[nt][2], b[nt][3]);
                }
            addrA += 32;   // k0 += 16 (bf16 -> 32 bytes)
            addrB += 32;
        }
    }
}

// ------------------------------ weight prep --------------------------------
__global__ void k_prep(const float* __restrict__ W1, const float* __restrict__ W2,
                       const float* __restrict__ Wd1) {
    int idx = blockIdx.x * blockDim.x + threadIdx.x;
    if (idx >= 4 * 16384) return;
    int mat = idx >> 14, e = idx & 16383;
    int n = e >> 7, k = e & 127;
    float x;
    if      (mat == 0) x = W1[k * 128 + n];
    else if (mat == 1) x = W2[k * 128 + n];
    else if (mat == 2) x = Wd1[k * 128 + n];
    else               x = Wd1[(128 + k) * 128 + n];
    __nv_bfloat16 hi = __float2bfloat16(x);
    float r = x - __bfloat162float(hi);
    g_Whi[mat][n * 128 + k] = hi;
    g_Wlo[mat][n * 128 + k] = __float2bfloat16(r);
}

// ------------------------------ gemm1 (mma) --------------------------------
// h1 = relu((t*deginv) @ W1 + b1)
__global__ __launch_bounds__(256)
void k_gemm1_mma(const float2* __restrict__ A2, const float* __restrict__ scale,
                 const float* __restrict__ bias, float* __restrict__ C, int M) {
    extern __shared__ char smem[];
    uint32_t sb = smem_u32(smem);
    int tid = threadIdx.x, wid = tid >> 5, lane = tid & 31;
    int m_base = blockIdx.x * 128;
    int m_off = (wid & 3) * 32, n_off = (wid >> 2) * 64;
    int gid = lane >> 2, tig = lane & 3;

    load_W(smem, g_Whi[0], g_Wlo[0], tid);
    split_A(smem, A2, scale, m_base, M, tid);
    __syncthreads();

    float acc[2][8][4];
#pragma unroll
    for (int mi = 0; mi < 2; mi++)
#pragma unroll
        for (int ni = 0; ni < 8; ni++)
#pragma unroll
            for (int j = 0; j < 4; j++) acc[mi][ni][j] = 0.f;

    mma_passes(sb, m_off, n_off, lane, acc);

#pragma unroll
    for (int ni = 0; ni < 8; ni++) {
        int col = n_off + ni * 8 + tig * 2;
        float2 bb = *(const float2*)&bias[col];
#pragma unroll
        for (int mi = 0; mi < 2; mi++) {
            int r0 = m_base + m_off + mi * 16 + gid;
            float* c = acc[mi][ni];
            if (r0 < M)
                *(float2*)&C[(size_t)r0 * 128 + col] =
                    make_float2(fmaxf(c[0] + bb.x, 0.f), fmaxf(c[1] + bb.y, 0.f));
            if (r0 + 8 < M)
                *(float2*)&C[(size_t)(r0 + 8) * 128 + col] =
                    make_float2(fmaxf(c[2] + bb.x, 0.f), fmaxf(c[3] + bb.y, 0.f));
        }
    }
}

// ------------------------- fused h2 / P / Q (mma) ---------------------------
__global__ __launch_bounds__(256)
void k_gemm3_mma(const float2* __restrict__ A2, const float* __restrict__ scale,
                 const float* __restrict__ b2, float* __restrict__ H2,
                 float* __restrict__ P, float* __restrict__ Q, int M) {
    extern __shared__ char smem[];
    uint32_t sb = smem_u32(smem);
    int tid = threadIdx.x, wid = tid >> 5, lane = tid & 31;
    int m_base = blockIdx.x * 128;
    int m_off = (wid & 3) * 32, n_off = (wid >> 2) * 64;
    int gid = lane >> 2, tig = lane & 3;

    float acc[2][8][4];

    // ---- phase 1: h2 = (t*deginv) @ W2 + b2 ----
    load_W(smem, g_Whi[1], g_Wlo[1], tid);
    split_A(smem, A2, scale, m_base, M, tid);
    __syncthreads();
#pragma unroll
    for (int mi = 0; mi < 2; mi++)
#pragma unroll
        for (int ni = 0; ni < 8; ni++)
#pragma unroll
            for (int j = 0; j < 4; j++) acc[mi][ni][j] = 0.f;
    mma_passes(sb, m_off, n_off, lane, acc);
    __syncthreads();   // everyone done reading A/W smem before we overwrite

    // epilogue: write H2, re-split h2 into A smem, reload W with Wd1_top
#pragma unroll
    for (int ni = 0; ni < 8; ni++) {
        int col = n_off + ni * 8 + tig * 2;
        float2 bb = *(const float2*)&b2[col];
#pragma unroll
        for (int mi = 0; mi < 2; mi++) {
            float* c = acc[mi][ni];
            float v0 = c[0] + bb.x, v1 = c[1] + bb.y;
            float v2 = c[2] + bb.x, v3 = c[3] + bb.y;
            int lr = m_off + mi * 16 + gid;
            int r0 = m_base + lr;
            if (r0 < M)     *(float2*)&H2[(size_t)r0 * 128 + col] = make_float2(v0, v1);
            if (r0 + 8 < M) *(float2*)&H2[(size_t)(r0 + 8) * 128 + col] = make_float2(v2, v3);
            // split into smem A tiles (rows lr and lr+8)
            __nv_bfloat16 h0 = __float2bfloat16(v0), h1 = __float2bfloat16(v1);
            __nv_bfloat16 h2b = __float2bfloat16(v2), h3 = __float2bfloat16(v3);
            __nv_bfloat16 l0 = __float2bfloat16(v0 - __bfloat162float(h0));
            __nv_bfloat16 l1 = __float2bfloat16(v1 - __bfloat162float(h1));
            __nv_bfloat16 l2 = __float2bfloat16(v2 - __bfloat162float(h2b));
            __nv_bfloat16 l3 = __float2bfloat16(v3 - __bfloat162float(h3));
            uint32_t o0 = lr * (PITCH * 2) + col * 2;
            uint32_t o1 = (lr + 8) * (PITCH * 2) + col * 2;
            *(uint32_t*)(smem + SM_AHI + o0) =
                ((uint32_t)__bfloat16_as_ushort(h1) << 16) | __bfloat16_as_ushort(h0);
            *(uint32_t*)(smem + SM_ALO + o0) =
                ((uint32_t)__bfloat16_as_ushort(l1) << 16) | __bfloat16_as_ushort(l0);
            *(uint32_t*)(smem + SM_AHI + o1) =
                ((uint32_t)__bfloat16_as_ushort(h3) << 16) | __bfloat16_as_ushort(h2b);
            *(uint32_t*)(smem + SM_ALO + o1) =
                ((uint32_t)__bfloat16_as_ushort(l3) << 16) | __bfloat16_as_ushort(l2);
        }
    }
    load_W(smem, g_Whi[2], g_Wlo[2], tid);
    __syncthreads();

    // ---- phase 2: P = h2 @ Wd1_top ----
#pragma unroll
    for (int mi = 0; mi < 2; mi++)
#pragma unroll
        for (int ni = 0; ni < 8; ni++)
#pragma unroll
            for (int j = 0; j < 4; j++) acc[mi][ni][j] = 0.f;
    mma_passes(sb, m_off, n_off, lane, acc);
    __syncthreads();
#pragma unroll
    for (int ni = 0; ni < 8; ni++) {
        int col = n_off + ni * 8 + tig * 2;
#pragma unroll
        for (int mi = 0; mi < 2; mi++) {
            float* c = acc[mi][ni];
            int r0 = m_base + m_off + mi * 16 + gid;
            if (r0 < M)     *(float2*)&P[(size_t)r0 * 128 + col] = make_float2(c[0], c[1]);
            if (r0 + 8 < M) *(float2*)&P[(size_t)(r0 + 8) * 128 + col] = make_float2(c[2], c[3]);
        }
    }
    load_W(smem, g_Whi[3], g_Wlo[3], tid);
    __syncthreads();

    // ---- phase 3: Q = h2 @ Wd1_bot ----
#pragma unroll
    for (int mi = 0; mi < 2; mi++)
#pragma unroll
        for (int ni = 0; ni < 8; ni++)
#pragma unroll
            for (int j = 0; j < 4; j++) acc[mi][ni][j] = 0.f;
    mma_passes(sb, m_off, n_off, lane, acc);
#pragma unroll
    for (int ni = 0; ni < 8; ni++) {
        int col = n_off + ni * 8 + tig * 2;
#pragma unroll
        for (int mi = 0; mi < 2; mi++) {
            float* c = acc[mi][ni];
            int r0 = m_base + m_off + mi * 16 + gid;
            if (r0 < M)     *(float2*)&Q[(size_t)r0 * 128 + col] = make_float2(c[0], c[1]);
            if (r0 + 8 < M) *(float2*)&Q[(size_t)(r0 + 8) * 128 + col] = make_float2(c[2], c[3]);
        }
    }
}

// -------------------------------- graph prep -------------------------------
__global__ void k_zero_cnt(int nn) {
    int i = blockIdx.x * blockDim.x + threadIdx.x;
    if (i < nn) g_cnt[i] = 0;
}

__global__ void k_build(const int2* __restrict__ idx, const float* __restrict__ val, int ne) {
    int e = blockIdx.x * blockDim.x + threadIdx.x;
    if (e >= ne) return;
    int2 rc = idx[e];
    float v = val[e];
    int slot = atomicAdd(&g_cnt[rc.x], 1);
    if (slot < CAP) {
        g_col[rc.x * CAP + slot] = rc.y;
        g_val[rc.x * CAP + slot] = v;
    }
}

__global__ void k_spmm(const float4* __restrict__ X, float4* __restrict__ Y,
                       float* __restrict__ deginv_out, int nn) {
    int w = (blockIdx.x * blockDim.x + threadIdx.x) >> 5;
    int lane = threadIdx.x & 31;
    if (w >= nn) return;
    int cnt = g_cnt[w];
    if (cnt > CAP) cnt = CAP;
    const int*   cols = &g_col[w * CAP];
    const float* vals = &g_val[w * CAP];
    float4 acc = make_float4(0.f, 0.f, 0.f, 0.f);
    float dsum = 0.f;
#pragma unroll 2
    for (int e = 0; e < cnt; e++) {
        int c = cols[e];
        float v = vals[e];
        float4 x = X[c * 32 + lane];
        acc.x += v * x.x; acc.y += v * x.y; acc.z += v * x.z; acc.w += v * x.w;
        dsum += v;
    }
    Y[w * 32 + lane] = acc;
    if (deginv_out != nullptr && lane == 0)
        deginv_out[w] = 1.0f / fmaxf(dsum, 1.0f);
}

// -------------------------------- decoder ----------------------------------
__global__ void k_decode2(const int* __restrict__ pu, const int* __restrict__ pv,
                          const int* __restrict__ nu, const int* __restrict__ nv,
                          const float4* __restrict__ P, const float4* __restrict__ Q,
                          const float* __restrict__ bd1, const float* __restrict__ Wd2,
                          const float* __restrict__ bd2, float* __restrict__ out, int NP) {
    int w = (blockIdx.x * blockDim.x + threadIdx.x) >> 5;
    int lane = threadIdx.x & 31;
    if (w >= 2 * NP) return;
    int u, v;
    if (w < NP) { u = pu[w]; v = pv[w]; }
    else        { u = nu[w - NP]; v = nv[w - NP]; }
    float4 p = P[u * 32 + lane];
    float4 q = Q[v * 32 + lane];
    float4 b = ((const float4*)bd1)[lane];
    float4 d = ((const float4*)Wd2)[lane];
    float h0 = fmaxf(p.x + q.x + b.x, 0.f);
    float h1 = fmaxf(p.y + q.y + b.y, 0.f);
    float h2 = fmaxf(p.z + q.z + b.z, 0.f);
    float h3 = fmaxf(p.w + q.w + b.w, 0.f);
    float s = h0 * d.x + h1 * d.y + h2 * d.z + h3 * d.w;
#pragma unroll
    for (int o = 16; o > 0; o >>= 1)
        s += __shfl_down_sync(0xffffffff, s, o);
    if (lane == 0) out[w] = s + bd2[0];
}

// -------------------------------- launcher ---------------------------------
extern "C" void kernel_launch(void* const* d_in, const int* in_sizes, int n_in,
                              void* d_out, int out_size) {
    int o = (n_in >= 16) ? 1 : 0;

    const int2*  adj   = (const int2*) d_in[0];
    const float* avals = (const float*)d_in[1];
    const float* h     = (const float*)d_in[2 + o];
    const int*   pos_u = (const int*)  d_in[3 + o];
    const int*   pos_v = (const int*)  d_in[4 + o];
    const int*   neg_u = (const int*)  d_in[5 + o];
    const int*   neg_v = (const int*)  d_in[6 + o];
    const float* W1    = (const float*)d_in[7 + o];
    const float* b1    = (const float*)d_in[8 + o];
    const float* W2    = (const float*)d_in[9 + o];
    const float* b2    = (const float*)d_in[10 + o];
    const float* Wd1   = (const float*)d_in[11 + o];
    const float* bd1   = (const float*)d_in[12 + o];
    const float* Wd2   = (const float*)d_in[13 + o];
    const float* bd2   = (const float*)d_in[14 + o];

    const int NE = in_sizes[1];
    const int NN = in_sizes[2 + o] / 128;
    const int NP = in_sizes[3 + o];

    float* out = (float*)d_out;
    float* pos_out = out;
    float* h2      = out + 2 * NP;

    static float* p_t = nullptr;
    static float* p_h1 = nullptr;
    static float* p_P = nullptr;
    static float* p_Q = nullptr;
    static float* p_deginv = nullptr;
    static bool init = false;
    if (!init) {
        cudaGetSymbolAddress((void**)&p_t, g_t);
        cudaGetSymbolAddress((void**)&p_h1, g_h1);
        cudaGetSymbolAddress((void**)&p_P, g_P);
        cudaGetSymbolAddress((void**)&p_Q, g_Q);
        cudaGetSymbolAddress((void**)&p_deginv, g_deginv);
        cudaFuncSetAttribute(k_gemm1_mma, cudaFuncAttributeMaxDynamicSharedMemorySize, SMEM_MMA);
        cudaFuncSetAttribute(k_gemm3_mma, cudaFuncAttributeMaxDynamicSharedMemorySize, SMEM_MMA);
        init = true;
    }

    int tcg = (NN + 127) / 128;

    k_zero_cnt<<<(NN + 255) / 256, 256>>>(NN);
    k_build<<<(NE + 255) / 256, 256>>>(adj, avals, NE);
    k_prep<<<(4 * 16384 + 255) / 256, 256>>>(W1, W2, Wd1);
    k_spmm<<<(NN * 32 + 255) / 256, 256>>>((const float4*)h, (float4*)p_t, p_deginv, NN);
    k_gemm1_mma<<<tcg, 256, SMEM_MMA>>>((const float2*)p_t, p_deginv, b1, p_h1, NN);
    k_spmm<<<(NN * 32 + 255) / 256, 256>>>((const float4*)p_h1, (float4*)p_t, nullptr, NN);
    k_gemm3_mma<<<tcg, 256, SMEM_MMA>>>((const float2*)p_t, p_deginv, b2, h2, p_P, p_Q, NN);
    k_decode2<<<(2 * NP * 32 + 255) / 256, 256>>>(pos_u, pos_v, neg_u, neg_v,
                                                  (const float4*)p_P, (const float4*)p_Q,
                                                  bd1, Wd2, bd2, pos_out, NP);
}